// round 1
// baseline (speedup 1.0000x reference)
#include <cuda_runtime.h>
#include <cuda_bf16.h>
#include <stdint.h>

// Problem constants
#define NR 4096            // N (rows in z1/z2)
#define DIM 1024
#define BM 128             // tile M = tile N
#define BK 32              // k-chunk
#define NKT (DIM / BK)     // 32 k iterations
#define NT (NR / BM)       // 32 tiles per dim
#define NTILES (NT * (NT + 1) / 2)   // 528 upper-tri tiles
#define LDS 40             // smem row stride in bf16 (80B: 16B-aligned, ldmatrix conflict-free)

// Scratch (static device globals; no runtime allocation)
__device__ __nv_bfloat16 g_zb[NR * DIM];   // normalized z1, bf16 (8 MB)
__device__ float g_sq[NR];                 // ||z1_i||^2 of normalized rows
__device__ float g_pos[NR];                // s_pos per row
__device__ float g_negpart[NTILES];        // per-tile partial sums of g_neg

__device__ __forceinline__ uint32_t su32(const void* p) {
    return (uint32_t)__cvta_generic_to_shared(p);
}

__device__ __forceinline__ void cpasync16(uint32_t dst, const void* g) {
    asm volatile("cp.async.cg.shared.global [%0], [%1], 16;" :: "r"(dst), "l"(g));
}

#define CP_COMMIT() asm volatile("cp.async.commit_group;")
#define CP_WAIT(n)  asm volatile("cp.async.wait_group %0;" :: "n"(n))

#define LDMX4(R, addr) \
    asm volatile("ldmatrix.sync.aligned.m8n8.x4.shared.b16 {%0,%1,%2,%3}, [%4];" \
                 : "=r"((R)[0]), "=r"((R)[1]), "=r"((R)[2]), "=r"((R)[3]) : "r"(addr))

__device__ __forceinline__ void mma16816(float* c, const uint32_t* a, const uint32_t* b) {
    asm volatile(
        "mma.sync.aligned.m16n8k16.row.col.f32.bf16.bf16.f32 "
        "{%0,%1,%2,%3}, {%4,%5,%6,%7}, {%8,%9}, {%0,%1,%2,%3};"
        : "+f"(c[0]), "+f"(c[1]), "+f"(c[2]), "+f"(c[3])
        : "r"(a[0]), "r"(a[1]), "r"(a[2]), "r"(a[3]), "r"(b[0]), "r"(b[1]));
}

// -------------------------------------------------------------------------
// Kernel 1: normalize rows, compute s_pos and sq, emit bf16 z1.
// One block per row pair (i, i+NR). 256 threads, 4 float4/thread pairs.
// -------------------------------------------------------------------------
__global__ __launch_bounds__(256) void normalize_kernel(const float* __restrict__ z) {
    int row = blockIdx.x;
    int tid = threadIdx.x;
    const float4* z1p = (const float4*)(z + (size_t)row * DIM);
    const float4* z2p = (const float4*)(z + (size_t)(row + NR) * DIM);
    float4 a = z1p[tid];
    float4 b = z2p[tid];

    float s1 = a.x * a.x + a.y * a.y + a.z * a.z + a.w * a.w;
    float s2 = b.x * b.x + b.y * b.y + b.z * b.z + b.w * b.w;
    #pragma unroll
    for (int o = 16; o; o >>= 1) {
        s1 += __shfl_xor_sync(0xFFFFFFFFu, s1, o);
        s2 += __shfl_xor_sync(0xFFFFFFFFu, s2, o);
    }
    __shared__ float sh1[8], sh2[8], sh3[8];
    int w = tid >> 5, l = tid & 31;
    if (l == 0) { sh1[w] = s1; sh2[w] = s2; }
    __syncthreads();
    s1 = 0.f; s2 = 0.f;
    #pragma unroll
    for (int i = 0; i < 8; i++) { s1 += sh1[i]; s2 += sh2[i]; }

    float inv1 = 1.f / fmaxf(sqrtf(s1), 1e-12f);
    float inv2 = 1.f / fmaxf(sqrtf(s2), 1e-12f);

    float ax = a.x * inv1, ay = a.y * inv1, az = a.z * inv1, aw = a.w * inv1;
    float bx = b.x * inv2, by = b.y * inv2, bz = b.z * inv2, bw = b.w * inv2;

    float dp = (ax - bx) * (ax - bx) + (ay - by) * (ay - by) +
               (az - bz) * (az - bz) + (aw - bw) * (aw - bw);
    #pragma unroll
    for (int o = 16; o; o >>= 1) dp += __shfl_xor_sync(0xFFFFFFFFu, dp, o);
    if (l == 0) sh3[w] = dp;
    __syncthreads();
    if (tid == 0) {
        float d = 0.f;
        #pragma unroll
        for (int i = 0; i < 8; i++) d += sh3[i];
        g_pos[row] = logf(expf(-0.5f * d) + 1e-8f) + 1.f;
        g_sq[row] = s1 * inv1 * inv1;
    }

    // write bf16 normalized z1 row
    __nv_bfloat162* dst = (__nv_bfloat162*)(g_zb + (size_t)row * DIM) + tid * 2;
    dst[0] = __floats2bfloat162_rn(ax, ay);
    dst[1] = __floats2bfloat162_rn(az, aw);
}

// -------------------------------------------------------------------------
// Kernel 2: upper-triangular tiled Gram GEMM + fused exp-reduce epilogue.
// 528 CTAs x 256 threads. 8 warps in 2x4; warp tile 64x32.
// -------------------------------------------------------------------------
__global__ __launch_bounds__(256) void gram_kernel() {
    __shared__ __nv_bfloat16 sA[2][BM * LDS];
    __shared__ __nv_bfloat16 sB[2][BM * LDS];

    int bid = blockIdx.x, tid = threadIdx.x;
    // map linear bid -> (ti, tj) with tj >= ti
    int ti = 0, rem = bid, rl = NT;
    while (rem >= rl) { rem -= rl; rl--; ti++; }
    int tj = ti + rem;

    int lane = tid & 31, warp = tid >> 5;
    int wr = warp >> 2, wc = warp & 3;

    const __nv_bfloat16* Abase = g_zb + (size_t)ti * BM * DIM;
    const __nv_bfloat16* Bbase = g_zb + (size_t)tj * BM * DIM;

    float acc[4][4][4];
    #pragma unroll
    for (int i = 0; i < 4; i++)
        #pragma unroll
        for (int j = 0; j < 4; j++)
            #pragma unroll
            for (int e = 0; e < 4; e++) acc[i][j][e] = 0.f;

    // --- async load helper (as a lambda-free macro-ish block) ---
    // each thread copies 2x 16B chunks per matrix per stage
    // task t in [0,512): row = t>>2, chunk = t&3
    #define ISSUE_STAGE(kt, buf)                                                  \
        do {                                                                      \
            _Pragma("unroll")                                                     \
            for (int t = tid; t < 512; t += 256) {                                \
                int r = t >> 2, c = t & 3;                                        \
                cpasync16(su32(&sA[buf][r * LDS + c * 8]),                        \
                          Abase + (size_t)r * DIM + (kt) * BK + c * 8);           \
                cpasync16(su32(&sB[buf][r * LDS + c * 8]),                        \
                          Bbase + (size_t)r * DIM + (kt) * BK + c * 8);           \
            }                                                                     \
            CP_COMMIT();                                                          \
        } while (0)

    ISSUE_STAGE(0, 0);

    int q = lane >> 3, rin = lane & 7;

    for (int kt = 0; kt < NKT; kt++) {
        int buf = kt & 1;
        if (kt < NKT - 1) {
            ISSUE_STAGE(kt + 1, buf ^ 1);
            CP_WAIT(1);
        } else {
            CP_WAIT(0);
        }
        __syncthreads();

        const __nv_bfloat16* A = sA[buf];
        const __nv_bfloat16* B = sB[buf];

        #pragma unroll
        for (int k16 = 0; k16 < BK; k16 += 16) {
            uint32_t afr[4][4];
            #pragma unroll
            for (int mi = 0; mi < 4; mi++) {
                int rr = wr * 64 + mi * 16 + ((q & 1) ? 8 : 0) + rin;
                int cc = k16 + ((q >= 2) ? 8 : 0);
                LDMX4(afr[mi], su32(&A[rr * LDS + cc]));
            }
            uint32_t bfr[4][2];
            #pragma unroll
            for (int nb = 0; nb < 2; nb++) {
                int rr = wc * 32 + nb * 16 + ((q >= 2) ? 8 : 0) + rin;
                int cc = k16 + ((q & 1) ? 8 : 0);
                uint32_t t4[4];
                LDMX4(t4, su32(&B[rr * LDS + cc]));
                bfr[nb * 2 + 0][0] = t4[0]; bfr[nb * 2 + 0][1] = t4[1];
                bfr[nb * 2 + 1][0] = t4[2]; bfr[nb * 2 + 1][1] = t4[3];
            }
            #pragma unroll
            for (int mi = 0; mi < 4; mi++)
                #pragma unroll
                for (int ni = 0; ni < 4; ni++)
                    mma16816(acc[mi][ni], afr[mi], bfr[ni]);
        }
        __syncthreads();
    }

    // ---- epilogue: star_neg contribution ----
    int r0 = lane >> 2, c0 = (lane & 3) * 2;
    float sqi[8], sqj[8];
    #pragma unroll
    for (int mi = 0; mi < 4; mi++) {
        sqi[mi * 2 + 0] = g_sq[ti * BM + wr * 64 + mi * 16 + r0];
        sqi[mi * 2 + 1] = g_sq[ti * BM + wr * 64 + mi * 16 + r0 + 8];
    }
    #pragma unroll
    for (int ni = 0; ni < 4; ni++) {
        sqj[ni * 2 + 0] = g_sq[tj * BM + wc * 32 + ni * 8 + c0];
        sqj[ni * 2 + 1] = g_sq[tj * BM + wc * 32 + ni * 8 + c0 + 1];
    }

    float local = 0.f;
    bool diag = (ti == tj);
    #pragma unroll
    for (int mi = 0; mi < 4; mi++) {
        #pragma unroll
        for (int ni = 0; ni < 4; ni++) {
            #pragma unroll
            for (int e = 0; e < 4; e++) {
                float dot = acc[mi][ni][e];
                float si = sqi[mi * 2 + (e >> 1)];
                float sj = sqj[ni * 2 + (e & 1)];
                float d2 = fmaxf(si + sj - 2.f * dot, 0.f);
                float g = __expf(-0.5f * d2);
                if (!diag) {
                    local += 2.f * g;   // count (i,j) and (j,i)
                } else {
                    int gi = wr * 64 + mi * 16 + r0 + ((e >> 1) ? 8 : 0);
                    int gj = wc * 32 + ni * 8 + c0 + (e & 1);
                    if (gi != gj) local += g;
                }
            }
        }
    }

    // deterministic block reduce
    #pragma unroll
    for (int o = 16; o; o >>= 1) local += __shfl_xor_sync(0xFFFFFFFFu, local, o);
    __shared__ float part[8];
    if (lane == 0) part[warp] = local;
    __syncthreads();
    if (tid == 0) {
        float tot = 0.f;
        #pragma unroll
        for (int i = 0; i < 8; i++) tot += part[i];
        g_negpart[bid] = tot;
    }
}

// -------------------------------------------------------------------------
// Kernel 3: deterministic finalize
// -------------------------------------------------------------------------
__global__ __launch_bounds__(256) void finalize_kernel(float* out) {
    __shared__ double sh[256];
    int tid = threadIdx.x;

    double p = 0.0;
    for (int i = tid; i < NR; i += 256) p += (double)g_pos[i];
    sh[tid] = p;
    __syncthreads();
    for (int s = 128; s; s >>= 1) {
        if (tid < s) sh[tid] += sh[tid + s];
        __syncthreads();
    }
    double pos_sum = sh[0];
    __syncthreads();

    double n = 0.0;
    for (int i = tid; i < NTILES; i += 256) n += (double)g_negpart[i];
    sh[tid] = n;
    __syncthreads();
    for (int s = 128; s; s >>= 1) {
        if (tid < s) sh[tid] += sh[tid + s];
        __syncthreads();
    }
    if (tid == 0) {
        double star_mean = sh[0] / ((double)NR * (double)(NR - 1)) + 1e-8;
        double loss = -(pos_sum / (double)NR) + 64.0 * star_mean;
        out[0] = (float)loss;
    }
}

extern "C" void kernel_launch(void* const* d_in, const int* in_sizes, int n_in,
                              void* d_out, int out_size) {
    const float* z = (const float*)d_in[0];
    float* out = (float*)d_out;
    normalize_kernel<<<NR, 256>>>(z);
    gram_kernel<<<NTILES, 256>>>();
    finalize_kernel<<<1, 256>>>(out);
}

// round 3
// speedup vs baseline: 1.0545x; 1.0545x over previous
#include <cuda_runtime.h>
#include <cuda_bf16.h>
#include <stdint.h>

// Problem constants
#define NR 4096
#define DIM 1024                     // also bytes/row in fp8
#define NBLK 272                     // 128x256 tiles covering j>=i
#define STAGE_BYTES 49152            // A: 128x128B (16KB) + B: 256x128B (32KB)
#define SMEM_TOTAL (2 * STAGE_BYTES) // 96KB double buffer

// Scratch (static device globals; no runtime allocation)
__device__ uint8_t g_zq[NR * DIM];   // normalized z1 * 16, e4m3 (4 MB, L2-resident)
__device__ float g_sq[NR];
__device__ float g_pos[NR];
__device__ float g_negpart[NBLK];

__device__ __forceinline__ uint32_t su32(const void* p) {
    return (uint32_t)__cvta_generic_to_shared(p);
}
__device__ __forceinline__ void cpasync16(uint32_t dst, const void* g) {
    asm volatile("cp.async.cg.shared.global [%0], [%1], 16;" :: "r"(dst), "l"(g));
}
#define CP_COMMIT() asm volatile("cp.async.commit_group;")
#define CP_WAIT(n)  asm volatile("cp.async.wait_group %0;" :: "n"(n))

#define LDMX4(R, addr) \
    asm volatile("ldmatrix.sync.aligned.m8n8.x4.shared.b16 {%0,%1,%2,%3}, [%4];" \
                 : "=r"((R)[0]), "=r"((R)[1]), "=r"((R)[2]), "=r"((R)[3]) : "r"(addr))

__device__ __forceinline__ void mma16832(float* c, const uint32_t* a, const uint32_t* b) {
    asm volatile(
        "mma.sync.aligned.m16n8k32.row.col.f32.e4m3.e4m3.f32 "
        "{%0,%1,%2,%3}, {%4,%5,%6,%7}, {%8,%9}, {%0,%1,%2,%3};"
        : "+f"(c[0]), "+f"(c[1]), "+f"(c[2]), "+f"(c[3])
        : "r"(a[0]), "r"(a[1]), "r"(a[2]), "r"(a[3]), "r"(b[0]), "r"(b[1]));
}

__device__ __forceinline__ uint32_t pack4_e4m3(float v0, float v1, float v2, float v3) {
    uint16_t h01, h23;
    asm("cvt.rn.satfinite.e4m3x2.f32 %0, %1, %2;" : "=h"(h01) : "f"(v1), "f"(v0));
    asm("cvt.rn.satfinite.e4m3x2.f32 %0, %1, %2;" : "=h"(h23) : "f"(v3), "f"(v2));
    return (uint32_t)h01 | ((uint32_t)h23 << 16);
}

// -------------------------------------------------------------------------
// Kernel 1: warp-per-row-pair normalize. Emits e4m3 (z * 16).
// -------------------------------------------------------------------------
__global__ __launch_bounds__(256) void normalize_kernel(const float* __restrict__ z) {
    int warp = threadIdx.x >> 5, lane = threadIdx.x & 31;
    int row = blockIdx.x * 8 + warp;

    const float4* z1p = (const float4*)(z + (size_t)row * DIM);
    const float4* z2p = (const float4*)(z + (size_t)(row + NR) * DIM);

    float4 a[8], b[8];
    #pragma unroll
    for (int i = 0; i < 8; i++) { a[i] = z1p[lane + 32 * i]; b[i] = z2p[lane + 32 * i]; }

    float s1 = 0.f, s2 = 0.f;
    #pragma unroll
    for (int i = 0; i < 8; i++) {
        s1 += a[i].x * a[i].x + a[i].y * a[i].y + a[i].z * a[i].z + a[i].w * a[i].w;
        s2 += b[i].x * b[i].x + b[i].y * b[i].y + b[i].z * b[i].z + b[i].w * b[i].w;
    }
    #pragma unroll
    for (int o = 16; o; o >>= 1) {
        s1 += __shfl_xor_sync(0xFFFFFFFFu, s1, o);
        s2 += __shfl_xor_sync(0xFFFFFFFFu, s2, o);
    }
    float inv1 = 1.f / fmaxf(sqrtf(s1), 1e-12f);
    float inv2 = 1.f / fmaxf(sqrtf(s2), 1e-12f);
    float q1 = 16.f * inv1;     // quantization scale folded in

    float dp = 0.f;
    uint32_t* dst = (uint32_t*)(g_zq + (size_t)row * DIM);
    #pragma unroll
    for (int i = 0; i < 8; i++) {
        float ax = a[i].x * inv1, ay = a[i].y * inv1, az = a[i].z * inv1, aw = a[i].w * inv1;
        float bx = b[i].x * inv2, by = b[i].y * inv2, bz = b[i].z * inv2, bw = b[i].w * inv2;
        dp += (ax - bx) * (ax - bx) + (ay - by) * (ay - by) +
              (az - bz) * (az - bz) + (aw - bw) * (aw - bw);
        dst[lane + 32 * i] = pack4_e4m3(a[i].x * q1, a[i].y * q1, a[i].z * q1, a[i].w * q1);
    }
    #pragma unroll
    for (int o = 16; o; o >>= 1) dp += __shfl_xor_sync(0xFFFFFFFFu, dp, o);
    if (lane == 0) {
        g_pos[row] = logf(__expf(-0.5f * dp) + 1e-8f) + 1.f;
        g_sq[row] = s1 * inv1 * inv1;
    }
}

// -------------------------------------------------------------------------
// Kernel 2: fp8 Gram (mma.sync m16n8k32 e4m3) + fused exp-reduce epilogue.
// 272 CTAs x 256 threads. CTA tile 128(M) x 256(N); warp tile 64x64.
// 8 K-stages of 128B, double-buffered cp.async, SW128 conflict-free.
// -------------------------------------------------------------------------
__global__ __launch_bounds__(256, 1) void gram_kernel() {
    extern __shared__ uint8_t dsm[];
    uint32_t smem_base = su32(dsm);
    int tid = threadIdx.x;
    int warp = tid >> 5, lane = tid & 31;
    int wr = warp >> 2, wc = warp & 3;   // warp grid 2 x 4

    // bid -> (ti, cs)
    int ti = 0, rem = blockIdx.x;
    #pragma unroll 1
    while (true) { int n = 16 - (ti >> 1); if (rem < n) break; rem -= n; ti++; }
    int cs = ((ti >> 1) + rem) * 256;

    const uint8_t* Abase = g_zq + (size_t)ti * 128 * DIM;
    const uint8_t* Bbase = g_zq + (size_t)cs * DIM;

    float acc[4][8][4];
    #pragma unroll
    for (int i = 0; i < 4; i++)
        #pragma unroll
        for (int j = 0; j < 8; j++)
            #pragma unroll
            for (int e = 0; e < 4; e++) acc[i][j][e] = 0.f;

    // stage s covers K bytes [s*128, s*128+128)
    #define LOAD_STAGE(s, slot)                                                   \
        do {                                                                      \
            uint32_t base_ = smem_base + (slot) * STAGE_BYTES;                    \
            const uint8_t* Ak = Abase + (s) * 128;                                \
            const uint8_t* Bk = Bbase + (s) * 128;                                \
            _Pragma("unroll")                                                     \
            for (int x = tid; x < 1024; x += 256) {                               \
                int r_ = x >> 3, c_ = x & 7;                                      \
                uint32_t off = (uint32_t)(r_ * 128 + c_ * 16);                    \
                off ^= (off >> 3) & 0x70;                                         \
                cpasync16(base_ + off, Ak + (size_t)r_ * DIM + c_ * 16);          \
            }                                                                     \
            _Pragma("unroll")                                                     \
            for (int x = tid; x < 2048; x += 256) {                               \
                int r_ = x >> 3, c_ = x & 7;                                      \
                uint32_t off = (uint32_t)(r_ * 128 + c_ * 16);                    \
                off ^= (off >> 3) & 0x70;                                         \
                cpasync16(base_ + 16384 + off, Bk + (size_t)r_ * DIM + c_ * 16);  \
            }                                                                     \
            CP_COMMIT();                                                          \
        } while (0)

    LOAD_STAGE(0, 0);
    LOAD_STAGE(1, 1);

    #pragma unroll 1
    for (int s = 0; s < 8; s++) {
        int slot = s & 1;
        if (s < 7) CP_WAIT(1); else CP_WAIT(0);
        __syncthreads();

        uint32_t sa = smem_base + slot * STAGE_BYTES;
        uint32_t sb = sa + 16384;

        #pragma unroll
        for (int kk = 0; kk < 4; kk++) {
            uint32_t af[4][4];
            #pragma unroll
            for (int mi = 0; mi < 4; mi++) {
                int r = wr * 64 + mi * 16 + (lane & 7) + ((lane >> 3) & 1) * 8;
                int cb = kk * 32 + ((lane >> 4) & 1) * 16;
                uint32_t off = (uint32_t)(r * 128 + cb);
                off ^= (off >> 3) & 0x70;
                LDMX4(af[mi], sa + off);
            }
            uint32_t bf[8][2];
            #pragma unroll
            for (int p = 0; p < 4; p++) {
                int r = wc * 64 + p * 16 + ((lane >> 4) & 1) * 8 + (lane & 7);
                int cb = kk * 32 + ((lane >> 3) & 1) * 16;
                uint32_t off = (uint32_t)(r * 128 + cb);
                off ^= (off >> 3) & 0x70;
                uint32_t t[4];
                LDMX4(t, sb + off);
                bf[2 * p + 0][0] = t[0]; bf[2 * p + 0][1] = t[1];
                bf[2 * p + 1][0] = t[2]; bf[2 * p + 1][1] = t[3];
            }
            #pragma unroll
            for (int mi = 0; mi < 4; mi++)
                #pragma unroll
                for (int ni = 0; ni < 8; ni++)
                    mma16832(acc[mi][ni], af[mi], bf[ni]);
        }

        if (s + 2 < 8) {
            __syncthreads();
            LOAD_STAGE(s + 2, slot);
        }
    }
    __syncthreads();   // buffers dead; reuse smem for sq staging

    float* sqi_sh = (float*)dsm;          // 128 floats
    float* sqj_sh = (float*)dsm + 128;    // 256 floats
    if (tid < 128) sqi_sh[tid] = g_sq[ti * 128 + tid];
    sqj_sh[tid] = g_sq[cs + tid];
    __syncthreads();

    // epilogue: acc holds 256 * dot. d2 = si + sj - acc/128.
    float local = 0.f;
    int r0 = lane >> 2, c0 = (lane & 3) * 2;
    #pragma unroll
    for (int mi = 0; mi < 4; mi++) {
        float si0 = sqi_sh[wr * 64 + mi * 16 + r0];
        float si1 = sqi_sh[wr * 64 + mi * 16 + r0 + 8];
        int gi0 = ti * 128 + wr * 64 + mi * 16 + r0;
        #pragma unroll
        for (int ni = 0; ni < 8; ni++) {
            int jl = wc * 64 + ni * 8 + c0;
            float sj0 = sqj_sh[jl], sj1 = sqj_sh[jl + 1];
            int gj0 = cs + jl;
            #pragma unroll
            for (int e = 0; e < 4; e++) {
                float si = (e >> 1) ? si1 : si0;
                float sj = (e & 1) ? sj1 : sj0;
                int gi = gi0 + ((e >> 1) ? 8 : 0);
                int gj = gj0 + (e & 1);
                float d2 = fmaxf(si + sj - acc[mi][ni][e] * (1.f / 128.f), 0.f);
                if (gj > gi) local += 2.f * __expf(-0.5f * d2);
            }
        }
    }

    #pragma unroll
    for (int o = 16; o; o >>= 1) local += __shfl_xor_sync(0xFFFFFFFFu, local, o);
    __shared__ float part[8];
    if (lane == 0) part[warp] = local;
    __syncthreads();
    if (tid == 0) {
        float tot = 0.f;
        #pragma unroll
        for (int i = 0; i < 8; i++) tot += part[i];
        g_negpart[blockIdx.x] = tot;
    }
}

// -------------------------------------------------------------------------
// Kernel 3: deterministic finalize
// -------------------------------------------------------------------------
__global__ __launch_bounds__(256) void finalize_kernel(float* out) {
    __shared__ double sh[256];
    int tid = threadIdx.x;

    double p = 0.0;
    for (int i = tid; i < NR; i += 256) p += (double)g_pos[i];
    sh[tid] = p;
    __syncthreads();
    for (int s = 128; s; s >>= 1) {
        if (tid < s) sh[tid] += sh[tid + s];
        __syncthreads();
    }
    double pos_sum = sh[0];
    __syncthreads();

    double n = 0.0;
    for (int i = tid; i < NBLK; i += 256) n += (double)g_negpart[i];
    sh[tid] = n;
    __syncthreads();
    for (int s = 128; s; s >>= 1) {
        if (tid < s) sh[tid] += sh[tid + s];
        __syncthreads();
    }
    if (tid == 0) {
        double star_mean = sh[0] / ((double)NR * (double)(NR - 1)) + 1e-8;
        double loss = -(pos_sum / (double)NR) + 64.0 * star_mean;
        out[0] = (float)loss;
    }
}

extern "C" void kernel_launch(void* const* d_in, const int* in_sizes, int n_in,
                              void* d_out, int out_size) {
    const float* z = (const float*)d_in[0];
    float* out = (float*)d_out;
    static int configured = 0;
    if (!configured) {
        cudaFuncSetAttribute(gram_kernel, cudaFuncAttributeMaxDynamicSharedMemorySize,
                             SMEM_TOTAL);
        configured = 1;
    }
    normalize_kernel<<<512, 256>>>(z);
    gram_kernel<<<NBLK, 256, SMEM_TOTAL>>>();
    finalize_kernel<<<1, 256>>>(out);
}